// round 15
// baseline (speedup 1.0000x reference)
#include <cuda_runtime.h>
#include <cuda_bf16.h>
#include <math.h>

// Problem constants
#define N_NODES 100000
#define N_EDGES 1600000
#define E_TOT   (N_EDGES + N_NODES)   // with self loops
#define IN_F    67
#define H1      10
#define C1      8
#define F1      (H1 * C1)             // 80
#define H1ST    128                   // h1x row stride: [0..80) features, [80..90) as1
#define AOFF    80                    // as1 offset within h1x row

#define SCAN_B  512
#define SCAN_NB ((N_NODES + SCAN_B - 1) / SCAN_B)   // 196

#define HIST_BLOCKS ((E_TOT + 255) / 256)           // 6641
#define GEMM_BLOCKS 1184

#define FLAG_AGG  (1ULL << 62)
#define FLAG_INC  (2ULL << 62)

// -------- scratch (static device globals; no allocation) --------
__device__ __align__(16) float g_h1x[N_NODES * H1ST];  // features + embedded a_src (row = 512B)
__device__ float  g_ad1[N_NODES * H1];    // a_dst layer1
__device__ float2 g_ha2[N_NODES];         // {h2, a_src2}
__device__ float  g_ad2[N_NODES];
__device__ int    g_deg[N_NODES];         // per-dst degree (self-resetting)
__device__ int    g_row[N_NODES + 1];     // CSR row offsets
__device__ int    g_cursor[N_NODES];      // scatter cursors (init = row offsets)
__device__ int    g_csr_src[E_TOT];       // src ids sorted by dst
__device__ volatile unsigned long long g_state[SCAN_NB];  // lookback state (self-resetting)

__device__ __forceinline__ float lrelu(float x) { return x > 0.0f ? x : 0.2f * x; }

// Per-block dtype detection: int64 little-endian with vals < 2^31 -> odd words zero.
__device__ __forceinline__ int detect_is64(const int* __restrict__ ei32) {
    bool is64 = true;
    #pragma unroll
    for (int k = 1; k < 16; k += 2) if (ei32[k] != 0) is64 = false;
    return is64 ? 1 : 0;
}

__device__ __forceinline__ void edge_sd(const void* __restrict__ ei, int is64,
                                        int e, int& s, int& d) {
    if (e < N_EDGES) {
        if (is64) {
            const long long* p = (const long long*)ei;
            s = (int)p[e]; d = (int)p[N_EDGES + e];
        } else {
            const int* p = (const int*)ei;
            s = p[e]; d = p[N_EDGES + e];
        }
        if ((unsigned)s >= N_NODES) s = 0;
        if ((unsigned)d >= N_NODES) d = 0;
    } else {
        s = e - N_EDGES; d = s;
    }
}

// dst-only read (for histogram)
__device__ __forceinline__ int edge_d(const void* __restrict__ ei, int is64, int e) {
    int d;
    if (e < N_EDGES) {
        if (is64) d = (int)((const long long*)ei)[N_EDGES + e];
        else      d = ((const int*)ei)[N_EDGES + e];
        if ((unsigned)d >= N_NODES) d = 0;
    } else {
        d = e - N_EDGES;
    }
    return d;
}

// -------- L0: fused histogram (blocks [0,HIST_BLOCKS)) + gemm1 (rest) --------
__global__ __launch_bounds__(256) void k_hist_gemm(
        const void* __restrict__ ei,
        const float* __restrict__ x, const float* __restrict__ W1,
        const float* __restrict__ att_src1, const float* __restrict__ att_dst1) {
    if (blockIdx.x < HIST_BLOCKS) {
        __shared__ int s_is64;
        if (threadIdx.x == 0) s_is64 = detect_is64((const int*)ei);
        __syncthreads();
        int e = blockIdx.x * 256 + threadIdx.x;
        if (e < E_TOT) atomicAdd(&g_deg[edge_d(ei, s_is64, e)], 1);
        return;
    }
    // ---- gemm part: 240 active threads = 3 nodes x 80 outputs ----
    int bid = blockIdx.x - HIST_BLOCKS;
    if (threadIdx.x >= 240) return;
    int t  = threadIdx.x % 80;
    int ny = threadIdx.x / 80;
    float w[IN_F];
    #pragma unroll
    for (int k = 0; k < IN_F; k++) w[k] = W1[k * F1 + t];
    float a_s = att_src1[t], a_d = att_dst1[t];
    __shared__ float xs[3][IN_F + 1];
    __shared__ float ps[3][F1], pd[3][F1];
    for (int base = bid * 3; base < N_NODES; base += GEMM_BLOCKS * 3) {
        int n = base + ny;
        if (n < N_NODES && t < IN_F) xs[ny][t] = x[n * IN_F + t];
        __syncthreads();
        if (n < N_NODES) {
            float acc = 0.0f;
            #pragma unroll
            for (int k = 0; k < IN_F; k++) acc = fmaf(xs[ny][k], w[k], acc);
            g_h1x[n * H1ST + t] = acc;
            ps[ny][t] = acc * a_s;
            pd[ny][t] = acc * a_d;
        }
        __syncthreads();
        if (n < N_NODES && t < H1) {
            float ss = 0.0f, sd = 0.0f;
            #pragma unroll
            for (int c = 0; c < C1; c++) { ss += ps[ny][t * C1 + c]; sd += pd[ny][t * C1 + c]; }
            g_h1x[n * H1ST + AOFF + t] = ss;   // embedded a_src
            g_ad1[n * H1 + t]          = sd;
        }
        __syncthreads();
    }
}

// -------- L1: single-launch exclusive scan (decoupled lookback) --------
__global__ __launch_bounds__(SCAN_B) void k_scan() {
    __shared__ int sm[SCAN_B];
    __shared__ int s_pref;
    int tid = threadIdx.x, b = blockIdx.x;
    int i = b * SCAN_B + tid;
    int v = (i < N_NODES) ? g_deg[i] : 0;
    if (i < N_NODES) g_deg[i] = 0;          // reset for next graph replay
    sm[tid] = v;
    __syncthreads();
    #pragma unroll
    for (int off = 1; off < SCAN_B; off <<= 1) {
        int add = (tid >= off) ? sm[tid - off] : 0;
        __syncthreads();
        sm[tid] += add;
        __syncthreads();
    }
    int total = sm[SCAN_B - 1];
    if (tid == 0) {
        if (b == 0) {
            atomicExch((unsigned long long*)&g_state[0], FLAG_INC | (unsigned)total);
            s_pref = 0;
        } else {
            atomicExch((unsigned long long*)&g_state[b], FLAG_AGG | (unsigned)total);
        }
    }
    if (b > 0 && tid < 32) {
        int lane = tid;
        int look = b - 1;
        int prefix = 0;
        while (true) {
            int k = look - lane;
            unsigned long long st;
            if (k >= 0) {
                do { st = g_state[k]; } while ((st >> 62) == 0);
            } else {
                st = FLAG_INC;
            }
            unsigned incmask = __ballot_sync(0xffffffffu, (st >> 62) == 2ULL);
            int val = (int)(st & 0xffffffffu);
            int contrib;
            if (incmask) {
                int L = __ffs(incmask) - 1;
                contrib = (lane <= L) ? val : 0;
            } else {
                contrib = val;
            }
            #pragma unroll
            for (int o = 16; o > 0; o >>= 1) contrib += __shfl_down_sync(0xffffffffu, contrib, o);
            contrib = __shfl_sync(0xffffffffu, contrib, 0);
            prefix += contrib;
            if (incmask) break;
            look -= 32;
        }
        if (lane == 0) {
            atomicExch((unsigned long long*)&g_state[b], FLAG_INC | (unsigned)(prefix + total));
            s_pref = prefix;
        }
    }
    __syncthreads();
    int pref = s_pref;
    if (i < N_NODES) {
        int r = pref + sm[tid] - v;
        g_row[i] = r;
        g_cursor[i] = r;
    }
    if (b == SCAN_NB - 1 && tid == SCAN_B - 1) g_row[N_NODES] = pref + total;
}

// -------- L2: scatter src ids into CSR, 2 edges/thread (+ state reset) --------
#define SCAT_BLOCKS ((E_TOT + 511) / 512)
__global__ void k_scatter(const void* __restrict__ ei) {
    __shared__ int s_is64;
    if (threadIdx.x == 0) s_is64 = detect_is64((const int*)ei);
    __syncthreads();
    int t = blockIdx.x * blockDim.x + threadIdx.x;
    if (t < SCAN_NB) g_state[t] = 0;                // reset for next graph replay
    int e0 = t * 2, e1 = t * 2 + 1;
    if (e0 < E_TOT) {
        int s, d; edge_sd(ei, s_is64, e0, s, d);
        int pos = atomicAdd(&g_cursor[d], 1);
        g_csr_src[pos] = s;
    }
    if (e1 < E_TOT) {
        int s, d; edge_sd(ei, s_is64, e1, s, d);
        int pos = atomicAdd(&g_cursor[d], 1);
        g_csr_src[pos] = s;
    }
}

// -------- L3: fused layer1 softmax+aggregate + layer2 prep, WARP per dst --------
// (exact R10 structure — empirically fastest variant)
// Feature map: lane owns f={2*lane, 2*lane+1} (head lane>>2) and, for lane<16,
// f2=64+lane (head 8+(lane>>3)). One float2 load + one shfl serve the pair.
#define FULLW 0xffffffffu
__global__ __launch_bounds__(256) void k_edge1(
        const float* __restrict__ b1, const float* __restrict__ W2,
        const float* __restrict__ att_src2, const float* __restrict__ att_dst2) {
    int d    = (blockIdx.x * blockDim.x + threadIdx.x) >> 5;
    int lane = threadIdx.x & 31;
    if (d >= N_NODES) return;

    int r0 = g_row[d], r1 = g_row[d + 1];
    float adv = (lane < H1) ? g_ad1[d * H1 + lane] : 0.0f;

    int hA = lane >> 2;            // head of features 2*lane, 2*lane+1
    int hB = 8 + (lane >> 3);      // head of feature 64+lane (lane<16)

    float accx = 0.0f, accy = 0.0f, acc2 = 0.0f;
    float den = 0.0f;              // lanes 0..9 hold per-head denominators

    for (int j = r0; j < r1; j += 32) {
        int nb = min(32, r1 - j);
        int s_pre = (j + lane < r1) ? g_csr_src[j + lane] : 0;
        for (int k = 0; k < nb; k++) {
            int s = __shfl_sync(FULLW, s_pre, k);
            const float* hp = &g_h1x[s << 7];
            float av = (lane < H1) ? hp[AOFF + lane] : 0.0f;
            float ex = __expf(lrelu(av + adv));
            den += ex;             // meaningful only in lanes 0..9
            float eA = __shfl_sync(FULLW, ex, hA);
            float eB = __shfl_sync(FULLW, ex, hB);
            float2 p01 = *(const float2*)(hp + 2 * lane);
            accx = fmaf(eA, p01.x, accx);
            accy = fmaf(eA, p01.y, accy);
            if (lane < 16) acc2 = fmaf(eB, hp[64 + lane], acc2);
        }
    }
    float dA = __shfl_sync(FULLW, den, hA);
    float dB = __shfl_sync(FULLW, den, hB);

    // ---- fused layer2 prep: bias + ELU + dot(W2) + warp reduce ----
    float v0 = accx / dA + b1[2 * lane];
    float v1 = accy / dA + b1[2 * lane + 1];
    v0 = v0 > 0.0f ? v0 : (__expf(v0) - 1.0f);
    v1 = v1 > 0.0f ? v1 : (__expf(v1) - 1.0f);
    float sum = v0 * W2[2 * lane] + v1 * W2[2 * lane + 1];
    if (lane < 16) {
        float v2 = acc2 / dB + b1[64 + lane];
        v2 = v2 > 0.0f ? v2 : (__expf(v2) - 1.0f);
        sum = fmaf(v2, W2[64 + lane], sum);
    }
    #pragma unroll
    for (int o = 16; o > 0; o >>= 1) sum += __shfl_down_sync(FULLW, sum, o);
    if (lane == 0) {
        g_ha2[d] = make_float2(sum, sum * att_src2[0]);
        g_ad2[d] = sum * att_dst2[0];
    }
}

// -------- L4: fused layer2 softmax+aggregate, warp per dst node --------
__global__ void k_edge2(const float* __restrict__ b2, float* __restrict__ out) {
    int d    = (blockIdx.x * blockDim.x + threadIdx.x) >> 5;
    int lane = threadIdx.x & 31;
    if (d >= N_NODES) return;
    int r0 = g_row[d], r1 = g_row[d + 1];
    float ad = g_ad2[d];
    float num = 0.0f, den = 0.0f;
    for (int j = r0 + lane; j < r1; j += 32) {
        int s = g_csr_src[j];
        float2 ha = g_ha2[s];
        float ex = __expf(lrelu(ha.y + ad));
        num = fmaf(ex, ha.x, num);
        den += ex;
    }
    #pragma unroll
    for (int o = 16; o > 0; o >>= 1) {
        num += __shfl_down_sync(0xffffffffu, num, o);
        den += __shfl_down_sync(0xffffffffu, den, o);
    }
    if (lane == 0) out[d] = num / den + b2[0];
}

extern "C" void kernel_launch(void* const* d_in, const int* in_sizes, int n_in,
                              void* d_out, int out_size) {
    const float* x    = (const float*)d_in[0];
    const void*  ei   = d_in[1];
    const float* W1   = (const float*)d_in[2];
    const float* as1  = (const float*)d_in[3];
    const float* ad1  = (const float*)d_in[4];
    const float* b1   = (const float*)d_in[5];
    const float* W2   = (const float*)d_in[6];
    const float* as2  = (const float*)d_in[7];
    const float* ad2  = (const float*)d_in[8];
    const float* b2   = (const float*)d_in[9];
    float* out = (float*)d_out;

    k_hist_gemm<<<HIST_BLOCKS + GEMM_BLOCKS, 256>>>(ei, x, W1, as1, ad1); // 0
    k_scan<<<SCAN_NB, SCAN_B>>>();                                         // 1
    k_scatter<<<SCAT_BLOCKS, 256>>>(ei);                                   // 2
    int blk_n = (N_NODES * 32 + 255) / 256;
    k_edge1<<<blk_n, 256>>>(b1, W2, as2, ad2);                             // 3  <- profiled
    k_edge2<<<blk_n, 256>>>(b2, out);                                      // 4
}

// round 16
// speedup vs baseline: 1.0001x; 1.0001x over previous
#include <cuda_runtime.h>
#include <cuda_bf16.h>
#include <math.h>

// Problem constants
#define N_NODES 100000
#define N_EDGES 1600000
#define E_TOT   (N_EDGES + N_NODES)   // with self loops
#define IN_F    67
#define H1      10
#define C1      8
#define F1      (H1 * C1)             // 80
#define H1ST    128                   // h1x row stride: [0..80) features, [80..90) as1
#define AOFF    80                    // as1 offset within h1x row

#define SCAN_B  512
#define SCAN_NB ((N_NODES + SCAN_B - 1) / SCAN_B)   // 196

#define HIST_BLOCKS ((E_TOT + 255) / 256)           // 6641
#define GEMM_BLOCKS 296

#define FLAG_AGG  (1ULL << 62)
#define FLAG_INC  (2ULL << 62)

// -------- scratch (static device globals; no allocation) --------
__device__ __align__(16) float g_h1x[N_NODES * H1ST];  // features + embedded a_src (row = 512B)
__device__ float  g_ad1[N_NODES * H1];    // a_dst layer1
__device__ float2 g_ha2[N_NODES];         // {h2, a_src2}
__device__ float  g_ad2[N_NODES];
__device__ int    g_deg[N_NODES];         // per-dst degree (self-resetting)
__device__ int    g_row[N_NODES + 1];     // CSR row offsets
__device__ int    g_cursor[N_NODES];      // scatter cursors (init = row offsets)
__device__ int    g_csr_src[E_TOT];       // src ids sorted by dst
__device__ volatile unsigned long long g_state[SCAN_NB];  // lookback state (self-resetting)

__device__ __forceinline__ float lrelu(float x) { return x > 0.0f ? x : 0.2f * x; }

// Per-block dtype detection: int64 little-endian with vals < 2^31 -> odd words zero.
__device__ __forceinline__ int detect_is64(const int* __restrict__ ei32) {
    bool is64 = true;
    #pragma unroll
    for (int k = 1; k < 16; k += 2) if (ei32[k] != 0) is64 = false;
    return is64 ? 1 : 0;
}

__device__ __forceinline__ void edge_sd(const void* __restrict__ ei, int is64,
                                        int e, int& s, int& d) {
    if (e < N_EDGES) {
        if (is64) {
            const long long* p = (const long long*)ei;
            s = (int)p[e]; d = (int)p[N_EDGES + e];
        } else {
            const int* p = (const int*)ei;
            s = p[e]; d = p[N_EDGES + e];
        }
        if ((unsigned)s >= N_NODES) s = 0;
        if ((unsigned)d >= N_NODES) d = 0;
    } else {
        s = e - N_EDGES; d = s;
    }
}

// dst-only read (for histogram)
__device__ __forceinline__ int edge_d(const void* __restrict__ ei, int is64, int e) {
    int d;
    if (e < N_EDGES) {
        if (is64) d = (int)((const long long*)ei)[N_EDGES + e];
        else      d = ((const int*)ei)[N_EDGES + e];
        if ((unsigned)d >= N_NODES) d = 0;
    } else {
        d = e - N_EDGES;
    }
    return d;
}

// -------- dummy probe kernel (shifts ncu capture slot onto hist_gemm) --------
__global__ void k_nop() {}

// -------- L0: fused histogram (blocks [0,HIST_BLOCKS)) + gemm1 (rest) --------
__global__ __launch_bounds__(256) void k_hist_gemm(
        const void* __restrict__ ei,
        const float* __restrict__ x, const float* __restrict__ W1,
        const float* __restrict__ att_src1, const float* __restrict__ att_dst1) {
    if (blockIdx.x < HIST_BLOCKS) {
        __shared__ int s_is64;
        if (threadIdx.x == 0) s_is64 = detect_is64((const int*)ei);
        __syncthreads();
        int e = blockIdx.x * 256 + threadIdx.x;
        if (e < E_TOT) atomicAdd(&g_deg[edge_d(ei, s_is64, e)], 1);
        return;
    }
    // ---- gemm part: 240 active threads = 3 nodes x 80 outputs ----
    int bid = blockIdx.x - HIST_BLOCKS;
    if (threadIdx.x >= 240) return;
    int t  = threadIdx.x % 80;
    int ny = threadIdx.x / 80;
    float w[IN_F];
    #pragma unroll
    for (int k = 0; k < IN_F; k++) w[k] = W1[k * F1 + t];
    float a_s = att_src1[t], a_d = att_dst1[t];
    __shared__ float xs[3][IN_F + 1];
    __shared__ float ps[3][F1], pd[3][F1];
    for (int base = bid * 3; base < N_NODES; base += GEMM_BLOCKS * 3) {
        int n = base + ny;
        if (n < N_NODES && t < IN_F) xs[ny][t] = x[n * IN_F + t];
        __syncthreads();
        if (n < N_NODES) {
            float acc = 0.0f;
            #pragma unroll
            for (int k = 0; k < IN_F; k++) acc = fmaf(xs[ny][k], w[k], acc);
            g_h1x[n * H1ST + t] = acc;
            ps[ny][t] = acc * a_s;
            pd[ny][t] = acc * a_d;
        }
        __syncthreads();
        if (n < N_NODES && t < H1) {
            float ss = 0.0f, sd = 0.0f;
            #pragma unroll
            for (int c = 0; c < C1; c++) { ss += ps[ny][t * C1 + c]; sd += pd[ny][t * C1 + c]; }
            g_h1x[n * H1ST + AOFF + t] = ss;   // embedded a_src
            g_ad1[n * H1 + t]          = sd;
        }
        __syncthreads();
    }
}

// -------- L1: single-launch exclusive scan (decoupled lookback) --------
__global__ __launch_bounds__(SCAN_B) void k_scan() {
    __shared__ int sm[SCAN_B];
    __shared__ int s_pref;
    int tid = threadIdx.x, b = blockIdx.x;
    int i = b * SCAN_B + tid;
    int v = (i < N_NODES) ? g_deg[i] : 0;
    if (i < N_NODES) g_deg[i] = 0;          // reset for next graph replay
    sm[tid] = v;
    __syncthreads();
    #pragma unroll
    for (int off = 1; off < SCAN_B; off <<= 1) {
        int add = (tid >= off) ? sm[tid - off] : 0;
        __syncthreads();
        sm[tid] += add;
        __syncthreads();
    }
    int total = sm[SCAN_B - 1];
    if (tid == 0) {
        if (b == 0) {
            atomicExch((unsigned long long*)&g_state[0], FLAG_INC | (unsigned)total);
            s_pref = 0;
        } else {
            atomicExch((unsigned long long*)&g_state[b], FLAG_AGG | (unsigned)total);
        }
    }
    if (b > 0 && tid < 32) {
        int lane = tid;
        int look = b - 1;
        int prefix = 0;
        while (true) {
            int k = look - lane;
            unsigned long long st;
            if (k >= 0) {
                do { st = g_state[k]; } while ((st >> 62) == 0);
            } else {
                st = FLAG_INC;
            }
            unsigned incmask = __ballot_sync(0xffffffffu, (st >> 62) == 2ULL);
            int val = (int)(st & 0xffffffffu);
            int contrib;
            if (incmask) {
                int L = __ffs(incmask) - 1;
                contrib = (lane <= L) ? val : 0;
            } else {
                contrib = val;
            }
            #pragma unroll
            for (int o = 16; o > 0; o >>= 1) contrib += __shfl_down_sync(0xffffffffu, contrib, o);
            contrib = __shfl_sync(0xffffffffu, contrib, 0);
            prefix += contrib;
            if (incmask) break;
            look -= 32;
        }
        if (lane == 0) {
            atomicExch((unsigned long long*)&g_state[b], FLAG_INC | (unsigned)(prefix + total));
            s_pref = prefix;
        }
    }
    __syncthreads();
    int pref = s_pref;
    if (i < N_NODES) {
        int r = pref + sm[tid] - v;
        g_row[i] = r;
        g_cursor[i] = r;
    }
    if (b == SCAN_NB - 1 && tid == SCAN_B - 1) g_row[N_NODES] = pref + total;
}

// -------- L2: scatter src ids into CSR (+ reset lookback state) --------
__global__ void k_scatter(const void* __restrict__ ei) {
    __shared__ int s_is64;
    if (threadIdx.x == 0) s_is64 = detect_is64((const int*)ei);
    __syncthreads();
    int e = blockIdx.x * blockDim.x + threadIdx.x;
    if (e < SCAN_NB) g_state[e] = 0;
    if (e >= E_TOT) return;
    int s, d; edge_sd(ei, s_is64, e, s, d);
    int pos = atomicAdd(&g_cursor[d], 1);
    g_csr_src[pos] = s;
}

// -------- L3: fused layer1 softmax+aggregate + layer2 prep, WARP per dst --------
// (exact R10 structure — empirically fastest variant)
#define FULLW 0xffffffffu
__global__ __launch_bounds__(256) void k_edge1(
        const float* __restrict__ b1, const float* __restrict__ W2,
        const float* __restrict__ att_src2, const float* __restrict__ att_dst2) {
    int d    = (blockIdx.x * blockDim.x + threadIdx.x) >> 5;
    int lane = threadIdx.x & 31;
    if (d >= N_NODES) return;

    int r0 = g_row[d], r1 = g_row[d + 1];
    float adv = (lane < H1) ? g_ad1[d * H1 + lane] : 0.0f;

    int hA = lane >> 2;            // head of features 2*lane, 2*lane+1
    int hB = 8 + (lane >> 3);      // head of feature 64+lane (lane<16)

    float accx = 0.0f, accy = 0.0f, acc2 = 0.0f;
    float den = 0.0f;              // lanes 0..9 hold per-head denominators

    for (int j = r0; j < r1; j += 32) {
        int nb = min(32, r1 - j);
        int s_pre = (j + lane < r1) ? g_csr_src[j + lane] : 0;
        for (int k = 0; k < nb; k++) {
            int s = __shfl_sync(FULLW, s_pre, k);
            const float* hp = &g_h1x[s << 7];
            float av = (lane < H1) ? hp[AOFF + lane] : 0.0f;
            float ex = __expf(lrelu(av + adv));
            den += ex;             // meaningful only in lanes 0..9
            float eA = __shfl_sync(FULLW, ex, hA);
            float eB = __shfl_sync(FULLW, ex, hB);
            float2 p01 = *(const float2*)(hp + 2 * lane);
            accx = fmaf(eA, p01.x, accx);
            accy = fmaf(eA, p01.y, accy);
            if (lane < 16) acc2 = fmaf(eB, hp[64 + lane], acc2);
        }
    }
    float dA = __shfl_sync(FULLW, den, hA);
    float dB = __shfl_sync(FULLW, den, hB);

    // ---- fused layer2 prep: bias + ELU + dot(W2) + warp reduce ----
    float v0 = accx / dA + b1[2 * lane];
    float v1 = accy / dA + b1[2 * lane + 1];
    v0 = v0 > 0.0f ? v0 : (__expf(v0) - 1.0f);
    v1 = v1 > 0.0f ? v1 : (__expf(v1) - 1.0f);
    float sum = v0 * W2[2 * lane] + v1 * W2[2 * lane + 1];
    if (lane < 16) {
        float v2 = acc2 / dB + b1[64 + lane];
        v2 = v2 > 0.0f ? v2 : (__expf(v2) - 1.0f);
        sum = fmaf(v2, W2[64 + lane], sum);
    }
    #pragma unroll
    for (int o = 16; o > 0; o >>= 1) sum += __shfl_down_sync(FULLW, sum, o);
    if (lane == 0) {
        g_ha2[d] = make_float2(sum, sum * att_src2[0]);
        g_ad2[d] = sum * att_dst2[0];
    }
}

// -------- L4: fused layer2 softmax+aggregate, warp per dst node --------
__global__ void k_edge2(const float* __restrict__ b2, float* __restrict__ out) {
    int d    = (blockIdx.x * blockDim.x + threadIdx.x) >> 5;
    int lane = threadIdx.x & 31;
    if (d >= N_NODES) return;
    int r0 = g_row[d], r1 = g_row[d + 1];
    float ad = g_ad2[d];
    float num = 0.0f, den = 0.0f;
    for (int j = r0 + lane; j < r1; j += 32) {
        int s = g_csr_src[j];
        float2 ha = g_ha2[s];
        float ex = __expf(lrelu(ha.y + ad));
        num = fmaf(ex, ha.x, num);
        den += ex;
    }
    #pragma unroll
    for (int o = 16; o > 0; o >>= 1) {
        num += __shfl_down_sync(0xffffffffu, num, o);
        den += __shfl_down_sync(0xffffffffu, den, o);
    }
    if (lane == 0) out[d] = num / den + b2[0];
}

extern "C" void kernel_launch(void* const* d_in, const int* in_sizes, int n_in,
                              void* d_out, int out_size) {
    const float* x    = (const float*)d_in[0];
    const void*  ei   = d_in[1];
    const float* W1   = (const float*)d_in[2];
    const float* as1  = (const float*)d_in[3];
    const float* ad1  = (const float*)d_in[4];
    const float* b1   = (const float*)d_in[5];
    const float* W2   = (const float*)d_in[6];
    const float* as2  = (const float*)d_in[7];
    const float* ad2  = (const float*)d_in[8];
    const float* b2   = (const float*)d_in[9];
    float* out = (float*)d_out;

    k_nop<<<1, 32>>>();                                                    // 0 (probe shift)
    k_nop<<<1, 32>>>();                                                    // 1 (probe shift)
    k_nop<<<1, 32>>>();                                                    // 2 (probe shift)
    k_hist_gemm<<<HIST_BLOCKS + GEMM_BLOCKS, 256>>>(ei, x, W1, as1, ad1); // 3  <- profiled
    k_scan<<<SCAN_NB, SCAN_B>>>();                                         // 4
    k_scatter<<<HIST_BLOCKS, 256>>>(ei);                                   // 5
    int blk_n = (N_NODES * 32 + 255) / 256;
    k_edge1<<<blk_n, 256>>>(b1, W2, as2, ad2);                             // 6
    k_edge2<<<blk_n, 256>>>(b2, out);                                      // 7
}

// round 17
// speedup vs baseline: 1.0292x; 1.0291x over previous
#include <cuda_runtime.h>
#include <cuda_bf16.h>
#include <math.h>

// Problem constants
#define N_NODES 100000
#define N_EDGES 1600000
#define E_TOT   (N_EDGES + N_NODES)   // with self loops
#define IN_F    67
#define H1      10
#define C1      8
#define F1      (H1 * C1)             // 80
#define H1ST    128                   // h1x row stride: [0..80) features, [80..90) as1
#define AOFF    80                    // as1 offset within h1x row

#define SCAN_B  512
#define SCAN_NB ((N_NODES + SCAN_B - 1) / SCAN_B)   // 196

#define HIST_BLOCKS ((E_TOT + 255) / 256)           // 6641
#define GEMM_BLOCKS 296

#define FLAG_AGG  (1ULL << 62)
#define FLAG_INC  (2ULL << 62)

// -------- scratch (static device globals; no allocation) --------
__device__ __align__(16) float g_h1x[N_NODES * H1ST];  // features + embedded a_src (row = 512B)
__device__ float  g_ad1[N_NODES * H1];    // a_dst layer1
__device__ float2 g_ha2[N_NODES];         // {h2, a_src2}
__device__ float  g_ad2[N_NODES];
__device__ int    g_deg[N_NODES];         // per-dst degree (self-resetting)
__device__ int    g_row[N_NODES + 1];     // CSR row offsets
__device__ int    g_cursor[N_NODES];      // scatter cursors (init = row offsets)
__device__ int    g_csr_src[E_TOT];       // src ids sorted by dst
__device__ volatile unsigned long long g_state[SCAN_NB];  // lookback state (self-resetting)

__device__ __forceinline__ float lrelu(float x) { return x > 0.0f ? x : 0.2f * x; }

// Per-block dtype detection: int64 little-endian with vals < 2^31 -> odd words zero.
__device__ __forceinline__ int detect_is64(const int* __restrict__ ei32) {
    bool is64 = true;
    #pragma unroll
    for (int k = 1; k < 16; k += 2) if (ei32[k] != 0) is64 = false;
    return is64 ? 1 : 0;
}

__device__ __forceinline__ void edge_sd(const void* __restrict__ ei, int is64,
                                        int e, int& s, int& d) {
    if (e < N_EDGES) {
        if (is64) {
            const long long* p = (const long long*)ei;
            s = (int)p[e]; d = (int)p[N_EDGES + e];
        } else {
            const int* p = (const int*)ei;
            s = p[e]; d = p[N_EDGES + e];
        }
        if ((unsigned)s >= N_NODES) s = 0;
        if ((unsigned)d >= N_NODES) d = 0;
    } else {
        s = e - N_EDGES; d = s;
    }
}

// dst-only read (for histogram)
__device__ __forceinline__ int edge_d(const void* __restrict__ ei, int is64, int e) {
    int d;
    if (e < N_EDGES) {
        if (is64) d = (int)((const long long*)ei)[N_EDGES + e];
        else      d = ((const int*)ei)[N_EDGES + e];
        if ((unsigned)d >= N_NODES) d = 0;
    } else {
        d = e - N_EDGES;
    }
    return d;
}

// -------- L0: histogram of dst degrees (low-reg, full occupancy) --------
__global__ __launch_bounds__(256) void k_hist(const void* __restrict__ ei) {
    __shared__ int s_is64;
    if (threadIdx.x == 0) s_is64 = detect_is64((const int*)ei);
    __syncthreads();
    int e = blockIdx.x * 256 + threadIdx.x;
    if (e < E_TOT) atomicAdd(&g_deg[edge_d(ei, s_is64, e)], 1);
}

// -------- L1: h1 = x @ W1 ; a_src/a_dst per node (register-heavy, few blocks) --------
__global__ __launch_bounds__(240) void k_gemm(
        const float* __restrict__ x, const float* __restrict__ W1,
        const float* __restrict__ att_src1, const float* __restrict__ att_dst1) {
    int t  = threadIdx.x % 80;
    int ny = threadIdx.x / 80;
    float w[IN_F];
    #pragma unroll
    for (int k = 0; k < IN_F; k++) w[k] = W1[k * F1 + t];
    float a_s = att_src1[t], a_d = att_dst1[t];
    __shared__ float xs[3][IN_F + 1];
    __shared__ float ps[3][F1], pd[3][F1];
    for (int base = blockIdx.x * 3; base < N_NODES; base += GEMM_BLOCKS * 3) {
        int n = base + ny;
        if (n < N_NODES && t < IN_F) xs[ny][t] = x[n * IN_F + t];
        __syncthreads();
        if (n < N_NODES) {
            float acc = 0.0f;
            #pragma unroll
            for (int k = 0; k < IN_F; k++) acc = fmaf(xs[ny][k], w[k], acc);
            g_h1x[n * H1ST + t] = acc;
            ps[ny][t] = acc * a_s;
            pd[ny][t] = acc * a_d;
        }
        __syncthreads();
        if (n < N_NODES && t < H1) {
            float ss = 0.0f, sd = 0.0f;
            #pragma unroll
            for (int c = 0; c < C1; c++) { ss += ps[ny][t * C1 + c]; sd += pd[ny][t * C1 + c]; }
            g_h1x[n * H1ST + AOFF + t] = ss;   // embedded a_src
            g_ad1[n * H1 + t]          = sd;
        }
        __syncthreads();
    }
}

// -------- L2: single-launch exclusive scan (decoupled lookback) --------
__global__ __launch_bounds__(SCAN_B) void k_scan() {
    __shared__ int sm[SCAN_B];
    __shared__ int s_pref;
    int tid = threadIdx.x, b = blockIdx.x;
    int i = b * SCAN_B + tid;
    int v = (i < N_NODES) ? g_deg[i] : 0;
    if (i < N_NODES) g_deg[i] = 0;          // reset for next graph replay
    sm[tid] = v;
    __syncthreads();
    #pragma unroll
    for (int off = 1; off < SCAN_B; off <<= 1) {
        int add = (tid >= off) ? sm[tid - off] : 0;
        __syncthreads();
        sm[tid] += add;
        __syncthreads();
    }
    int total = sm[SCAN_B - 1];
    if (tid == 0) {
        if (b == 0) {
            atomicExch((unsigned long long*)&g_state[0], FLAG_INC | (unsigned)total);
            s_pref = 0;
        } else {
            atomicExch((unsigned long long*)&g_state[b], FLAG_AGG | (unsigned)total);
        }
    }
    if (b > 0 && tid < 32) {
        int lane = tid;
        int look = b - 1;
        int prefix = 0;
        while (true) {
            int k = look - lane;
            unsigned long long st;
            if (k >= 0) {
                do { st = g_state[k]; } while ((st >> 62) == 0);
            } else {
                st = FLAG_INC;
            }
            unsigned incmask = __ballot_sync(0xffffffffu, (st >> 62) == 2ULL);
            int val = (int)(st & 0xffffffffu);
            int contrib;
            if (incmask) {
                int L = __ffs(incmask) - 1;
                contrib = (lane <= L) ? val : 0;
            } else {
                contrib = val;
            }
            #pragma unroll
            for (int o = 16; o > 0; o >>= 1) contrib += __shfl_down_sync(0xffffffffu, contrib, o);
            contrib = __shfl_sync(0xffffffffu, contrib, 0);
            prefix += contrib;
            if (incmask) break;
            look -= 32;
        }
        if (lane == 0) {
            atomicExch((unsigned long long*)&g_state[b], FLAG_INC | (unsigned)(prefix + total));
            s_pref = prefix;
        }
    }
    __syncthreads();
    int pref = s_pref;
    if (i < N_NODES) {
        int r = pref + sm[tid] - v;
        g_row[i] = r;
        g_cursor[i] = r;
    }
    if (b == SCAN_NB - 1 && tid == SCAN_B - 1) g_row[N_NODES] = pref + total;
}

// -------- L3: scatter src ids into CSR (+ reset lookback state) --------
__global__ void k_scatter(const void* __restrict__ ei) {
    __shared__ int s_is64;
    if (threadIdx.x == 0) s_is64 = detect_is64((const int*)ei);
    __syncthreads();
    int e = blockIdx.x * blockDim.x + threadIdx.x;
    if (e < SCAN_NB) g_state[e] = 0;
    if (e >= E_TOT) return;
    int s, d; edge_sd(ei, s_is64, e, s, d);
    int pos = atomicAdd(&g_cursor[d], 1);
    g_csr_src[pos] = s;
}

// -------- L4: fused layer1 softmax+aggregate + layer2 prep, WARP per dst --------
// (exact R10 structure — empirically fastest variant)
#define FULLW 0xffffffffu
__global__ __launch_bounds__(256) void k_edge1(
        const float* __restrict__ b1, const float* __restrict__ W2,
        const float* __restrict__ att_src2, const float* __restrict__ att_dst2) {
    int d    = (blockIdx.x * blockDim.x + threadIdx.x) >> 5;
    int lane = threadIdx.x & 31;
    if (d >= N_NODES) return;

    int r0 = g_row[d], r1 = g_row[d + 1];
    float adv = (lane < H1) ? g_ad1[d * H1 + lane] : 0.0f;

    int hA = lane >> 2;            // head of features 2*lane, 2*lane+1
    int hB = 8 + (lane >> 3);      // head of feature 64+lane (lane<16)

    float accx = 0.0f, accy = 0.0f, acc2 = 0.0f;
    float den = 0.0f;              // lanes 0..9 hold per-head denominators

    for (int j = r0; j < r1; j += 32) {
        int nb = min(32, r1 - j);
        int s_pre = (j + lane < r1) ? g_csr_src[j + lane] : 0;
        for (int k = 0; k < nb; k++) {
            int s = __shfl_sync(FULLW, s_pre, k);
            const float* hp = &g_h1x[s << 7];
            float av = (lane < H1) ? hp[AOFF + lane] : 0.0f;
            float ex = __expf(lrelu(av + adv));
            den += ex;             // meaningful only in lanes 0..9
            float eA = __shfl_sync(FULLW, ex, hA);
            float eB = __shfl_sync(FULLW, ex, hB);
            float2 p01 = *(const float2*)(hp + 2 * lane);
            accx = fmaf(eA, p01.x, accx);
            accy = fmaf(eA, p01.y, accy);
            if (lane < 16) acc2 = fmaf(eB, hp[64 + lane], acc2);
        }
    }
    float dA = __shfl_sync(FULLW, den, hA);
    float dB = __shfl_sync(FULLW, den, hB);

    // ---- fused layer2 prep: bias + ELU + dot(W2) + warp reduce ----
    float v0 = accx / dA + b1[2 * lane];
    float v1 = accy / dA + b1[2 * lane + 1];
    v0 = v0 > 0.0f ? v0 : (__expf(v0) - 1.0f);
    v1 = v1 > 0.0f ? v1 : (__expf(v1) - 1.0f);
    float sum = v0 * W2[2 * lane] + v1 * W2[2 * lane + 1];
    if (lane < 16) {
        float v2 = acc2 / dB + b1[64 + lane];
        v2 = v2 > 0.0f ? v2 : (__expf(v2) - 1.0f);
        sum = fmaf(v2, W2[64 + lane], sum);
    }
    #pragma unroll
    for (int o = 16; o > 0; o >>= 1) sum += __shfl_down_sync(FULLW, sum, o);
    if (lane == 0) {
        g_ha2[d] = make_float2(sum, sum * att_src2[0]);
        g_ad2[d] = sum * att_dst2[0];
    }
}

// -------- L5: fused layer2 softmax+aggregate, warp per dst node --------
__global__ void k_edge2(const float* __restrict__ b2, float* __restrict__ out) {
    int d    = (blockIdx.x * blockDim.x + threadIdx.x) >> 5;
    int lane = threadIdx.x & 31;
    if (d >= N_NODES) return;
    int r0 = g_row[d], r1 = g_row[d + 1];
    float ad = g_ad2[d];
    float num = 0.0f, den = 0.0f;
    for (int j = r0 + lane; j < r1; j += 32) {
        int s = g_csr_src[j];
        float2 ha = g_ha2[s];
        float ex = __expf(lrelu(ha.y + ad));
        num = fmaf(ex, ha.x, num);
        den += ex;
    }
    #pragma unroll
    for (int o = 16; o > 0; o >>= 1) {
        num += __shfl_down_sync(0xffffffffu, num, o);
        den += __shfl_down_sync(0xffffffffu, den, o);
    }
    if (lane == 0) out[d] = num / den + b2[0];
}

extern "C" void kernel_launch(void* const* d_in, const int* in_sizes, int n_in,
                              void* d_out, int out_size) {
    const float* x    = (const float*)d_in[0];
    const void*  ei   = d_in[1];
    const float* W1   = (const float*)d_in[2];
    const float* as1  = (const float*)d_in[3];
    const float* ad1  = (const float*)d_in[4];
    const float* b1   = (const float*)d_in[5];
    const float* W2   = (const float*)d_in[6];
    const float* as2  = (const float*)d_in[7];
    const float* ad2  = (const float*)d_in[8];
    const float* b2   = (const float*)d_in[9];
    float* out = (float*)d_out;

    k_hist<<<HIST_BLOCKS, 256>>>(ei);                                      // 0
    k_gemm<<<GEMM_BLOCKS, 240>>>(x, W1, as1, ad1);                         // 1
    k_scan<<<SCAN_NB, SCAN_B>>>();                                         // 2
    k_scatter<<<HIST_BLOCKS, 256>>>(ei);                                   // 3  <- profiled
    int blk_n = (N_NODES * 32 + 255) / 256;
    k_edge1<<<blk_n, 256>>>(b1, W2, as2, ad2);                             // 4
    k_edge2<<<blk_n, 256>>>(b2, out);                                      // 5
}